// round 4
// baseline (speedup 1.0000x reference)
#include <cuda_runtime.h>
#include <cuda_fp16.h>
#include <cstdint>

// Problem constants
#define B  4
#define C  64
#define H  256
#define W  256
#define HW (H*W)              // 65536
#define NPIX (B*HW)           // 262144 source pixels
#define NIMG (C*HW)           // 4194304 image elements (fp16 -> 8 MB)

// Image in fp16, [H, W, C] layout: half index = (y*W + x)*C + c.
// Groups of 8 consecutive channels are 16B-aligned -> v4.f16x2 vector REDs.
__device__ uint4  g_image[NIMG / 8];   // 8 MB of fp16
__device__ double g_acc[2];            // [0]=sum, [1]=sumsq

// ---------------------------------------------------------------------------
// Packing + RED helpers
// ---------------------------------------------------------------------------
__device__ __forceinline__ unsigned int pack2(float a, float b) {
    __half2 h = __floats2half2_rn(a, b);
    return *reinterpret_cast<unsigned int*>(&h);
}

template<int N>
__device__ __forceinline__ void fire(__half* ptr, const float* w) {
    if constexpr (N == 8) {
        unsigned int r0 = pack2(w[0], w[1]), r1 = pack2(w[2], w[3]);
        unsigned int r2 = pack2(w[4], w[5]), r3 = pack2(w[6], w[7]);
        asm volatile("red.global.add.noftz.v4.f16x2 [%0], {%1,%2,%3,%4};"
                     :: "l"(ptr), "r"(r0), "r"(r1), "r"(r2), "r"(r3) : "memory");
    } else if constexpr (N == 4) {
        unsigned int r0 = pack2(w[0], w[1]), r1 = pack2(w[2], w[3]);
        asm volatile("red.global.add.noftz.v2.f16x2 [%0], {%1,%2};"
                     :: "l"(ptr), "r"(r0), "r"(r1) : "memory");
    } else if constexpr (N == 2) {
        unsigned int r0 = pack2(w[0], w[1]);
        asm volatile("red.global.add.noftz.f16x2 [%0], %1;"
                     :: "l"(ptr), "r"(r0) : "memory");
    } else {
        __half hv = __float2half_rn(w[0]);
        unsigned short us = *reinterpret_cast<unsigned short*>(&hv);
        asm volatile("red.global.add.noftz.f16 [%0], %1;"
                     :: "l"(ptr), "h"(us) : "memory");
    }
}

// Deposit N channels' 4 bilinear corners. cb = image base + channel offset.
template<int N>
__device__ __forceinline__ void corners(int X0, int Y0, __half* cb,
                                        const float* w00, const float* w10,
                                        const float* w01, const float* w11) {
    const bool vx0 = (X0 >= 0)  & (X0 < W);
    const bool vx1 = (X0 >= -1) & (X0 < W - 1);
    if ((Y0 >= 0) & (Y0 < H)) {
        __half* row = cb + (size_t)(Y0 * W) * C;
        if (vx0) fire<N>(row + (size_t)X0 * C,       w00);
        if (vx1) fire<N>(row + (size_t)(X0 + 1) * C, w10);
    }
    if ((Y0 >= -1) & (Y0 < H - 1)) {
        __half* row = cb + (size_t)((Y0 + 1) * W) * C;
        if (vx0) fire<N>(row + (size_t)X0 * C,       w01);
        if (vx1) fire<N>(row + (size_t)(X0 + 1) * C, w11);
    }
}

// ---------------------------------------------------------------------------
// Kernel 1: zero image + accumulators
// ---------------------------------------------------------------------------
__global__ void zero_kernel() {
    int i = blockIdx.x * blockDim.x + threadIdx.x;
    if (i < NIMG / 8) g_image[i] = make_uint4(0u, 0u, 0u, 0u);
    if (i == 0) { g_acc[0] = 0.0; g_acc[1] = 0.0; }
}

// ---------------------------------------------------------------------------
// Kernel 2: forward bilinear splat, 8 channels at a time (fp16 image).
// Displacement is linear (monotone) in c, so endpoint cells decide uniformity.
// Hierarchy on straddle: 8 -> 4 -> 2 -> 1 channels per RED.
// ---------------------------------------------------------------------------
__global__ void __launch_bounds__(256) splat_kernel(
    const float* __restrict__ flow,
    const float* __restrict__ spike)
{
    int idx = blockIdx.x * blockDim.x + threadIdx.x;
    if (idx >= NPIX) return;

    const int b = idx >> 16;
    const int p = idx & (HW - 1);
    const int y = p >> 8;
    const int x = p & (W - 1);

    const float u = flow[(size_t)b * 2 * HW + p];
    const float v = flow[(size_t)b * 2 * HW + HW + p];
    const float* sp = spike + (size_t)b * C * HW + p;

    const float xf = (float)x;
    const float yf = (float)y;

    __half* img = reinterpret_cast<__half*>(g_image);

    #pragma unroll 1
    for (int g = 0; g < C / 8; ++g) {
        float w00[8], w10[8], w01[8], w11[8];
        int   x0[8], y0[8];

        #pragma unroll
        for (int k = 0; k < 8; ++k) {
            const int c = g * 8 + k;
            const float val = __ldg(sp + (size_t)c * HW);
            const float s   = ((float)c - 31.5f) * (1.0f / 64.0f);
            const float xn  = fmaf(u, s, xf);
            const float yn  = fmaf(v, s, yf);
            const float fx  = floorf(xn);
            const float fy  = floorf(yn);
            const float wx  = xn - fx;
            const float wy  = yn - fy;
            x0[k] = (int)fx;
            y0[k] = (int)fy;
            const float a  = val * wx;      // val*wx
            const float bb = val - a;       // val*(1-wx)
            const float q  = 1.0f - wy;
            w00[k] = bb * q;
            w10[k] = a  * q;
            w01[k] = bb * wy;
            w11[k] = a  * wy;
        }

        __half* gbase = img + g * 8;

        if ((x0[0] == x0[7]) & (y0[0] == y0[7])) {
            corners<8>(x0[0], y0[0], gbase, w00, w10, w01, w11);
        } else {
            #pragma unroll
            for (int h = 0; h < 2; ++h) {
                const int o = 4 * h;
                if ((x0[o] == x0[o + 3]) & (y0[o] == y0[o + 3])) {
                    corners<4>(x0[o], y0[o], gbase + o,
                               w00 + o, w10 + o, w01 + o, w11 + o);
                } else {
                    #pragma unroll
                    for (int q2 = 0; q2 < 2; ++q2) {
                        const int o2 = o + 2 * q2;
                        if ((x0[o2] == x0[o2 + 1]) & (y0[o2] == y0[o2 + 1])) {
                            corners<2>(x0[o2], y0[o2], gbase + o2,
                                       w00 + o2, w10 + o2, w01 + o2, w11 + o2);
                        } else {
                            corners<1>(x0[o2], y0[o2], gbase + o2,
                                       w00 + o2, w10 + o2, w01 + o2, w11 + o2);
                            corners<1>(x0[o2 + 1], y0[o2 + 1], gbase + o2 + 1,
                                       w00 + o2 + 1, w10 + o2 + 1,
                                       w01 + o2 + 1, w11 + o2 + 1);
                        }
                    }
                }
            }
        }
    }
}

// ---------------------------------------------------------------------------
// Kernel 3: sum and sum-of-squares over the fp16 image (double accumulation).
// ---------------------------------------------------------------------------
__global__ void __launch_bounds__(256) reduce_kernel() {
    double s = 0.0, s2 = 0.0;
    const int stride = gridDim.x * blockDim.x;
    for (int i = blockIdx.x * blockDim.x + threadIdx.x; i < NIMG / 8; i += stride) {
        uint4 q = g_image[i];
        float2 f0 = __half22float2(*reinterpret_cast<__half2*>(&q.x));
        float2 f1 = __half22float2(*reinterpret_cast<__half2*>(&q.y));
        float2 f2 = __half22float2(*reinterpret_cast<__half2*>(&q.z));
        float2 f3 = __half22float2(*reinterpret_cast<__half2*>(&q.w));
        s  += (double)f0.x + (double)f0.y + (double)f1.x + (double)f1.y
            + (double)f2.x + (double)f2.y + (double)f3.x + (double)f3.y;
        s2 += (double)f0.x * f0.x + (double)f0.y * f0.y
            + (double)f1.x * f1.x + (double)f1.y * f1.y
            + (double)f2.x * f2.x + (double)f2.y * f2.y
            + (double)f3.x * f3.x + (double)f3.y * f3.y;
    }
    #pragma unroll
    for (int o = 16; o > 0; o >>= 1) {
        s  += __shfl_down_sync(0xFFFFFFFFu, s,  o);
        s2 += __shfl_down_sync(0xFFFFFFFFu, s2, o);
    }
    __shared__ double sh[2][8];
    int lane = threadIdx.x & 31;
    int wid  = threadIdx.x >> 5;
    if (lane == 0) { sh[0][wid] = s; sh[1][wid] = s2; }
    __syncthreads();
    if (wid == 0) {
        s  = (lane < 8) ? sh[0][lane] : 0.0;
        s2 = (lane < 8) ? sh[1][lane] : 0.0;
        #pragma unroll
        for (int o = 4; o > 0; o >>= 1) {
            s  += __shfl_down_sync(0xFFFFFFFFu, s,  o);
            s2 += __shfl_down_sync(0xFFFFFFFFu, s2, o);
        }
        if (lane == 0) {
            atomicAdd(&g_acc[0], s);
            atomicAdd(&g_acc[1], s2);
        }
    }
}

// ---------------------------------------------------------------------------
// Kernel 4: final loss = -var(image, ddof=1)
// ---------------------------------------------------------------------------
__global__ void final_kernel(float* out) {
    const double sum   = g_acc[0];
    const double sumsq = g_acc[1];
    const double Nd    = (double)NIMG;
    const double var   = (sumsq - sum * sum / Nd) / (Nd - 1.0);
    out[0] = (float)(-var);
}

// ---------------------------------------------------------------------------
extern "C" void kernel_launch(void* const* d_in, const int* in_sizes, int n_in,
                              void* d_out, int out_size)
{
    const float* flow;
    const float* spike;
    if (in_sizes[0] == 2 * NPIX) {
        flow  = (const float*)d_in[0];
        spike = (const float*)d_in[1];
    } else {
        flow  = (const float*)d_in[1];
        spike = (const float*)d_in[0];
    }
    float* out = (float*)d_out;

    zero_kernel<<<(NIMG / 8 + 255) / 256, 256>>>();
    splat_kernel<<<(NPIX + 255) / 256, 256>>>(flow, spike);
    reduce_kernel<<<1024, 256>>>();
    final_kernel<<<1, 1>>>(out);
}

// round 5
// speedup vs baseline: 1.0888x; 1.0888x over previous
#include <cuda_runtime.h>
#include <cstdint>

// Problem constants
#define B  4
#define C  64
#define H  256
#define W  256
#define HW (H*W)              // 65536
#define NPIX (B*HW)           // 262144 source pixels
#define NIMG (C*HW)           // 4194304 image elements

#define RGRID 296             // reduce grid (2 waves on 148 SMs)

// Scratch image in [H, W, C] layout: index = (y*W + x)*C + c.
// 4-channel groups are contiguous & 16B aligned -> float4 vector REDs.
// __device__ globals are zero-initialized at load; reduce_final re-zeroes
// everything it consumes, so every kernel_launch call sees clean state.
__device__ float        g_image[NIMG];   // 16 MB
__device__ double       g_acc[2];        // [0]=sum, [1]=sumsq
__device__ unsigned int g_count;         // block completion counter

// ---------------------------------------------------------------------------
// Kernel 1: forward bilinear splat, 4 channels per float4 RED.
// One thread per source pixel (b,y,x); loops over 16 channel groups.
// Displacement u*s_c is monotone in c -> endpoint channels decide whether the
// whole 4-group shares one corner cell (~94% with this flow distribution).
// ---------------------------------------------------------------------------
__global__ void __launch_bounds__(256) splat_kernel(
    const float* __restrict__ flow,
    const float* __restrict__ spike)
{
    const int idx = blockIdx.x * blockDim.x + threadIdx.x;   // grid exact

    const int b = idx >> 16;          // / HW
    const int p = idx & (HW - 1);     // % HW
    const int y = p >> 8;             // / W
    const int x = p & (W - 1);        // % W

    const float u = flow[(size_t)b * 2 * HW + p];
    const float v = flow[(size_t)b * 2 * HW + HW + p];
    const float* sp = spike + (size_t)b * C * HW + p;

    const float xf = (float)x;
    const float yf = (float)y;

    #pragma unroll
    for (int g = 0; g < C / 4; ++g) {
        float val[4], wx[4], wy[4];
        int   x0[4], y0[4];

        #pragma unroll
        for (int k = 0; k < 4; ++k) {
            const int c = g * 4 + k;
            val[k] = __ldg(sp + (size_t)c * HW);
            const float s  = ((float)c - 31.5f) * (1.0f / 64.0f);
            const float xn = fmaf(u, s, xf);
            const float yn = fmaf(v, s, yf);
            const float fx = floorf(xn);
            const float fy = floorf(yn);
            wx[k] = xn - fx;
            wy[k] = yn - fy;
            x0[k] = (int)fx;
            y0[k] = (int)fy;
        }

        if ((x0[0] == x0[3]) & (y0[0] == y0[3])) {
            const int X0 = x0[0], Y0 = y0[0];

            float4 w00, w10, w01, w11;
            {
                float a0 = val[0] * wx[0], b0 = val[0] - a0;   // a=val*wx, b=val*(1-wx)
                float a1 = val[1] * wx[1], b1 = val[1] - a1;
                float a2 = val[2] * wx[2], b2 = val[2] - a2;
                float a3 = val[3] * wx[3], b3 = val[3] - a3;
                float q0 = 1.0f - wy[0], q1 = 1.0f - wy[1];
                float q2 = 1.0f - wy[2], q3 = 1.0f - wy[3];
                w00 = make_float4(b0*q0,    b1*q1,    b2*q2,    b3*q3);
                w10 = make_float4(a0*q0,    a1*q1,    a2*q2,    a3*q3);
                w01 = make_float4(b0*wy[0], b1*wy[1], b2*wy[2], b3*wy[3]);
                w11 = make_float4(a0*wy[0], a1*wy[1], a2*wy[2], a3*wy[3]);
            }

            const bool vx0 = (X0 >= 0)  & (X0 < W);
            const bool vx1 = (X0 >= -1) & (X0 < W - 1);

            float* base = g_image + g * 4;
            if (Y0 >= 0 && Y0 < H) {
                float* row = base + (size_t)(Y0 * W) * C;
                if (vx0) atomicAdd(reinterpret_cast<float4*>(row + (size_t)X0 * C),       w00);
                if (vx1) atomicAdd(reinterpret_cast<float4*>(row + (size_t)(X0 + 1) * C), w10);
            }
            if (Y0 >= -1 && Y0 < H - 1) {
                float* row = base + (size_t)((Y0 + 1) * W) * C;
                if (vx0) atomicAdd(reinterpret_cast<float4*>(row + (size_t)X0 * C),       w01);
                if (vx1) atomicAdd(reinterpret_cast<float4*>(row + (size_t)(X0 + 1) * C), w11);
            }
        } else {
            // Slow path: per-channel scalar atomics (~6% of groups).
            #pragma unroll
            for (int k = 0; k < 4; ++k) {
                const int X0 = x0[k], Y0 = y0[k];
                const float a  = val[k] * wx[k];
                const float bb = val[k] - a;
                const float q  = 1.0f - wy[k];

                const bool vx0 = (X0 >= 0)  & (X0 < W);
                const bool vx1 = (X0 >= -1) & (X0 < W - 1);

                float* chan = g_image + g * 4 + k;
                if (Y0 >= 0 && Y0 < H) {
                    float* row = chan + (size_t)(Y0 * W) * C;
                    if (vx0) atomicAdd(row + (size_t)X0 * C,       bb * q);
                    if (vx1) atomicAdd(row + (size_t)(X0 + 1) * C, a  * q);
                }
                if (Y0 >= -1 && Y0 < H - 1) {
                    float* row = chan + (size_t)((Y0 + 1) * W) * C;
                    if (vx0) atomicAdd(row + (size_t)X0 * C,       bb * wy[k]);
                    if (vx1) atomicAdd(row + (size_t)(X0 + 1) * C, a  * wy[k]);
                }
            }
        }
    }
}

// ---------------------------------------------------------------------------
// Kernel 2: fused reduce + finalize.
// Reads the image (sum, sumsq in double), re-zeroes it for the next replay,
// and the last block computes loss = -var(ddof=1), writes out, resets state.
// ---------------------------------------------------------------------------
__global__ void __launch_bounds__(256) reduce_final_kernel(float* __restrict__ out) {
    double s = 0.0, s2 = 0.0;
    const int stride = RGRID * 256;
    float4* img4 = reinterpret_cast<float4*>(g_image);
    const float4 z4 = make_float4(0.f, 0.f, 0.f, 0.f);

    for (int i = blockIdx.x * blockDim.x + threadIdx.x; i < NIMG / 4; i += stride) {
        float4 v = img4[i];
        img4[i] = z4;                              // re-zero for next replay
        s  += (double)v.x + (double)v.y + (double)v.z + (double)v.w;
        s2 += (double)v.x * v.x + (double)v.y * v.y
            + (double)v.z * v.z + (double)v.w * v.w;
    }

    // intra-block reduction
    #pragma unroll
    for (int o = 16; o > 0; o >>= 1) {
        s  += __shfl_down_sync(0xFFFFFFFFu, s,  o);
        s2 += __shfl_down_sync(0xFFFFFFFFu, s2, o);
    }
    __shared__ double sh[2][8];
    const int lane = threadIdx.x & 31;
    const int wid  = threadIdx.x >> 5;
    if (lane == 0) { sh[0][wid] = s; sh[1][wid] = s2; }
    __syncthreads();

    __shared__ bool is_last;
    if (threadIdx.x == 0) {
        double bs = 0.0, bs2 = 0.0;
        #pragma unroll
        for (int w = 0; w < 8; ++w) { bs += sh[0][w]; bs2 += sh[1][w]; }
        atomicAdd(&g_acc[0], bs);
        atomicAdd(&g_acc[1], bs2);
        __threadfence();
        unsigned int t = atomicAdd(&g_count, 1u);
        is_last = (t == RGRID - 1);
    }
    __syncthreads();

    if (is_last && threadIdx.x == 0) {
        const double sum   = g_acc[0];
        const double sumsq = g_acc[1];
        const double Nd    = (double)NIMG;
        const double var   = (sumsq - sum * sum / Nd) / (Nd - 1.0);
        out[0] = (float)(-var);
        // reset for next replay
        g_acc[0] = 0.0;
        g_acc[1] = 0.0;
        g_count  = 0u;
    }
}

// ---------------------------------------------------------------------------
extern "C" void kernel_launch(void* const* d_in, const int* in_sizes, int n_in,
                              void* d_out, int out_size)
{
    const float* flow;
    const float* spike;
    if (in_sizes[0] == 2 * NPIX) {
        flow  = (const float*)d_in[0];
        spike = (const float*)d_in[1];
    } else {
        flow  = (const float*)d_in[1];
        spike = (const float*)d_in[0];
    }
    float* out = (float*)d_out;

    splat_kernel<<<NPIX / 256, 256>>>(flow, spike);
    reduce_final_kernel<<<RGRID, 256>>>(out);
}

// round 6
// speedup vs baseline: 1.2588x; 1.1561x over previous
#include <cuda_runtime.h>
#include <cstdint>

// Problem constants
#define B  4
#define C  64
#define H  256
#define W  256
#define HW (H*W)              // 65536
#define NPIX (B*HW)           // 262144 source pixels
#define NIMG (C*HW)           // 4194304 image elements

#define RGRID 1184            // reduce grid: 8 CTAs/SM on 148 SMs

// Scratch image in [H, W, C] layout: index = (y*W + x)*C + c.
// 4-channel groups are contiguous & 16B aligned -> float4 vector REDs.
// __device__ globals are zero-initialized at load; reduce_final re-zeroes
// everything it consumes, so every kernel_launch call sees clean state.
__device__ float        g_image[NIMG];   // 16 MB
__device__ double       g_acc[2];        // [0]=sum, [1]=sumsq
__device__ unsigned int g_count;         // block completion counter

// ---------------------------------------------------------------------------
// Kernel 1: forward bilinear splat, 4 channels per float4 RED.
// One thread per source pixel (b,y,x); loops over 16 channel groups.
// Displacement u*s_c is monotone in c -> endpoint channels decide whether the
// whole 4-group shares one corner cell (~94% with this flow distribution).
// At the REDG lane-rate model (1.29 cyc/lane/SM) this kernel is at its floor.
// ---------------------------------------------------------------------------
__global__ void __launch_bounds__(256) splat_kernel(
    const float* __restrict__ flow,
    const float* __restrict__ spike)
{
    const int idx = blockIdx.x * blockDim.x + threadIdx.x;   // grid exact

    const int b = idx >> 16;          // / HW
    const int p = idx & (HW - 1);     // % HW
    const int y = p >> 8;             // / W
    const int x = p & (W - 1);        // % W

    const float u = flow[(size_t)b * 2 * HW + p];
    const float v = flow[(size_t)b * 2 * HW + HW + p];
    const float* sp = spike + (size_t)b * C * HW + p;

    const float xf = (float)x;
    const float yf = (float)y;

    #pragma unroll
    for (int g = 0; g < C / 4; ++g) {
        float val[4], wx[4], wy[4];
        int   x0[4], y0[4];

        #pragma unroll
        for (int k = 0; k < 4; ++k) {
            const int c = g * 4 + k;
            val[k] = __ldg(sp + (size_t)c * HW);
            const float s  = ((float)c - 31.5f) * (1.0f / 64.0f);
            const float xn = fmaf(u, s, xf);
            const float yn = fmaf(v, s, yf);
            const float fx = floorf(xn);
            const float fy = floorf(yn);
            wx[k] = xn - fx;
            wy[k] = yn - fy;
            x0[k] = (int)fx;
            y0[k] = (int)fy;
        }

        if ((x0[0] == x0[3]) & (y0[0] == y0[3])) {
            const int X0 = x0[0], Y0 = y0[0];

            float4 w00, w10, w01, w11;
            {
                float a0 = val[0] * wx[0], b0 = val[0] - a0;   // a=val*wx, b=val*(1-wx)
                float a1 = val[1] * wx[1], b1 = val[1] - a1;
                float a2 = val[2] * wx[2], b2 = val[2] - a2;
                float a3 = val[3] * wx[3], b3 = val[3] - a3;
                float q0 = 1.0f - wy[0], q1 = 1.0f - wy[1];
                float q2 = 1.0f - wy[2], q3 = 1.0f - wy[3];
                w00 = make_float4(b0*q0,    b1*q1,    b2*q2,    b3*q3);
                w10 = make_float4(a0*q0,    a1*q1,    a2*q2,    a3*q3);
                w01 = make_float4(b0*wy[0], b1*wy[1], b2*wy[2], b3*wy[3]);
                w11 = make_float4(a0*wy[0], a1*wy[1], a2*wy[2], a3*wy[3]);
            }

            const bool vx0 = (X0 >= 0)  & (X0 < W);
            const bool vx1 = (X0 >= -1) & (X0 < W - 1);

            float* base = g_image + g * 4;
            if (Y0 >= 0 && Y0 < H) {
                float* row = base + (size_t)(Y0 * W) * C;
                if (vx0) atomicAdd(reinterpret_cast<float4*>(row + (size_t)X0 * C),       w00);
                if (vx1) atomicAdd(reinterpret_cast<float4*>(row + (size_t)(X0 + 1) * C), w10);
            }
            if (Y0 >= -1 && Y0 < H - 1) {
                float* row = base + (size_t)((Y0 + 1) * W) * C;
                if (vx0) atomicAdd(reinterpret_cast<float4*>(row + (size_t)X0 * C),       w01);
                if (vx1) atomicAdd(reinterpret_cast<float4*>(row + (size_t)(X0 + 1) * C), w11);
            }
        } else {
            // Slow path: per-channel scalar atomics (~6% of groups).
            #pragma unroll
            for (int k = 0; k < 4; ++k) {
                const int X0 = x0[k], Y0 = y0[k];
                const float a  = val[k] * wx[k];
                const float bb = val[k] - a;
                const float q  = 1.0f - wy[k];

                const bool vx0 = (X0 >= 0)  & (X0 < W);
                const bool vx1 = (X0 >= -1) & (X0 < W - 1);

                float* chan = g_image + g * 4 + k;
                if (Y0 >= 0 && Y0 < H) {
                    float* row = chan + (size_t)(Y0 * W) * C;
                    if (vx0) atomicAdd(row + (size_t)X0 * C,       bb * q);
                    if (vx1) atomicAdd(row + (size_t)(X0 + 1) * C, a  * q);
                }
                if (Y0 >= -1 && Y0 < H - 1) {
                    float* row = chan + (size_t)((Y0 + 1) * W) * C;
                    if (vx0) atomicAdd(row + (size_t)X0 * C,       bb * wy[k]);
                    if (vx1) atomicAdd(row + (size_t)(X0 + 1) * C, a  * wy[k]);
                }
            }
        }
    }
}

// ---------------------------------------------------------------------------
// Kernel 2: fused reduce + finalize.
// fp32 accumulation in the inner loop (each thread covers only ~14 elements,
// values O(1) -> fp32 partials are exact to ~1e-7), promoted to double at the
// warp level. Re-zeroes the image for the next graph replay. Last block
// computes loss = -var(ddof=1), writes out, resets state.
// ---------------------------------------------------------------------------
__global__ void __launch_bounds__(256) reduce_final_kernel(float* __restrict__ out) {
    float fs = 0.0f, fs2 = 0.0f;
    const int stride = RGRID * 256;
    float4* img4 = reinterpret_cast<float4*>(g_image);
    const float4 z4 = make_float4(0.f, 0.f, 0.f, 0.f);

    for (int i = blockIdx.x * blockDim.x + threadIdx.x; i < NIMG / 4; i += stride) {
        float4 v = img4[i];
        img4[i] = z4;                              // re-zero for next replay
        fs  += (v.x + v.y) + (v.z + v.w);
        fs2 += fmaf(v.x, v.x, v.y * v.y) + fmaf(v.z, v.z, v.w * v.w);
    }

    double s  = (double)fs;
    double s2 = (double)fs2;

    // intra-warp reduction (double)
    #pragma unroll
    for (int o = 16; o > 0; o >>= 1) {
        s  += __shfl_down_sync(0xFFFFFFFFu, s,  o);
        s2 += __shfl_down_sync(0xFFFFFFFFu, s2, o);
    }
    __shared__ double sh[2][8];
    const int lane = threadIdx.x & 31;
    const int wid  = threadIdx.x >> 5;
    if (lane == 0) { sh[0][wid] = s; sh[1][wid] = s2; }
    __syncthreads();

    __shared__ bool is_last;
    if (threadIdx.x == 0) {
        double bs = 0.0, bs2 = 0.0;
        #pragma unroll
        for (int w = 0; w < 8; ++w) { bs += sh[0][w]; bs2 += sh[1][w]; }
        atomicAdd(&g_acc[0], bs);
        atomicAdd(&g_acc[1], bs2);
        __threadfence();
        unsigned int t = atomicAdd(&g_count, 1u);
        is_last = (t == RGRID - 1);
    }
    __syncthreads();

    if (is_last && threadIdx.x == 0) {
        const double sum   = g_acc[0];
        const double sumsq = g_acc[1];
        const double Nd    = (double)NIMG;
        const double var   = (sumsq - sum * sum / Nd) / (Nd - 1.0);
        out[0] = (float)(-var);
        // reset for next replay
        g_acc[0] = 0.0;
        g_acc[1] = 0.0;
        g_count  = 0u;
    }
}

// ---------------------------------------------------------------------------
extern "C" void kernel_launch(void* const* d_in, const int* in_sizes, int n_in,
                              void* d_out, int out_size)
{
    const float* flow;
    const float* spike;
    if (in_sizes[0] == 2 * NPIX) {
        flow  = (const float*)d_in[0];
        spike = (const float*)d_in[1];
    } else {
        flow  = (const float*)d_in[1];
        spike = (const float*)d_in[0];
    }
    float* out = (float*)d_out;

    splat_kernel<<<NPIX / 256, 256>>>(flow, spike);
    reduce_final_kernel<<<RGRID, 256>>>(out);
}

// round 7
// speedup vs baseline: 1.5012x; 1.1926x over previous
#include <cuda_runtime.h>
#include <cstdint>

// Problem constants
#define B  4
#define C  64
#define H  256
#define W  256
#define HW (H*W)              // 65536
#define NPIX (B*HW)           // 262144 source pixels
#define NIMG (C*HW)           // 4194304 image elements

#define RGRID 1024            // reduce grid: 1024*256 threads * 4 float4 = NIMG exactly

// Scratch image as float4 per (group, y, x): img4[g*HW + y*W + x] holds
// channels {4g..4g+3} of pixel (y,x). Warp lanes are consecutive x, so a
// warp's 32 float4 REDs to one corner are CONTIGUOUS (4 cache lines, not 32).
// __device__ globals are zero-initialized at load; reduce_final re-zeroes
// everything it consumes, so every kernel_launch call sees clean state.
__device__ float4       g_image4[NIMG / 4];   // 16 MB
__device__ double       g_acc[2];             // [0]=sum, [1]=sumsq
__device__ unsigned int g_count;              // block completion counter

// ---------------------------------------------------------------------------
// Kernel 1: forward bilinear splat, 4 channels per float4 RED.
// One thread per source pixel (b,y,x); loops over 16 channel groups.
// Displacement u*s_c is monotone in c -> endpoint channels decide whether the
// whole 4-group shares one corner cell (~94% with this flow distribution).
// ---------------------------------------------------------------------------
__global__ void __launch_bounds__(256) splat_kernel(
    const float* __restrict__ flow,
    const float* __restrict__ spike)
{
    const int idx = blockIdx.x * blockDim.x + threadIdx.x;   // grid exact

    const int b = idx >> 16;          // / HW
    const int p = idx & (HW - 1);     // % HW
    const int y = p >> 8;             // / W
    const int x = p & (W - 1);        // % W

    const float u = flow[(size_t)b * 2 * HW + p];
    const float v = flow[(size_t)b * 2 * HW + HW + p];
    const float* sp = spike + (size_t)b * C * HW + p;

    const float xf = (float)x;
    const float yf = (float)y;

    #pragma unroll
    for (int g = 0; g < C / 4; ++g) {
        float val[4], wx[4], wy[4];
        int   x0[4], y0[4];

        #pragma unroll
        for (int k = 0; k < 4; ++k) {
            const int c = g * 4 + k;
            val[k] = __ldg(sp + (size_t)c * HW);
            const float s  = ((float)c - 31.5f) * (1.0f / 64.0f);
            const float xn = fmaf(u, s, xf);
            const float yn = fmaf(v, s, yf);
            const float fx = floorf(xn);
            const float fy = floorf(yn);
            wx[k] = xn - fx;
            wy[k] = yn - fy;
            x0[k] = (int)fx;
            y0[k] = (int)fy;
        }

        float4* plane = g_image4 + (size_t)g * HW;

        if ((x0[0] == x0[3]) & (y0[0] == y0[3])) {
            const int X0 = x0[0], Y0 = y0[0];

            float4 w00, w10, w01, w11;
            {
                float a0 = val[0] * wx[0], b0 = val[0] - a0;   // a=val*wx, b=val*(1-wx)
                float a1 = val[1] * wx[1], b1 = val[1] - a1;
                float a2 = val[2] * wx[2], b2 = val[2] - a2;
                float a3 = val[3] * wx[3], b3 = val[3] - a3;
                float q0 = 1.0f - wy[0], q1 = 1.0f - wy[1];
                float q2 = 1.0f - wy[2], q3 = 1.0f - wy[3];
                w00 = make_float4(b0*q0,    b1*q1,    b2*q2,    b3*q3);
                w10 = make_float4(a0*q0,    a1*q1,    a2*q2,    a3*q3);
                w01 = make_float4(b0*wy[0], b1*wy[1], b2*wy[2], b3*wy[3]);
                w11 = make_float4(a0*wy[0], a1*wy[1], a2*wy[2], a3*wy[3]);
            }

            const bool vx0 = (X0 >= 0)  & (X0 < W);
            const bool vx1 = (X0 >= -1) & (X0 < W - 1);

            if (Y0 >= 0 && Y0 < H) {
                float4* row = plane + Y0 * W;
                if (vx0) atomicAdd(row + X0,     w00);
                if (vx1) atomicAdd(row + X0 + 1, w10);
            }
            if (Y0 >= -1 && Y0 < H - 1) {
                float4* row = plane + (Y0 + 1) * W;
                if (vx0) atomicAdd(row + X0,     w01);
                if (vx1) atomicAdd(row + X0 + 1, w11);
            }
        } else {
            // Slow path: per-channel scalar atomics (~6% of groups).
            float* pf = reinterpret_cast<float*>(plane);
            #pragma unroll
            for (int k = 0; k < 4; ++k) {
                const int X0 = x0[k], Y0 = y0[k];
                const float a  = val[k] * wx[k];
                const float bb = val[k] - a;
                const float q  = 1.0f - wy[k];

                const bool vx0 = (X0 >= 0)  & (X0 < W);
                const bool vx1 = (X0 >= -1) & (X0 < W - 1);

                if (Y0 >= 0 && Y0 < H) {
                    float* row = pf + (size_t)(Y0 * W) * 4 + k;
                    if (vx0) atomicAdd(row + (size_t)X0 * 4,       bb * q);
                    if (vx1) atomicAdd(row + (size_t)(X0 + 1) * 4, a  * q);
                }
                if (Y0 >= -1 && Y0 < H - 1) {
                    float* row = pf + (size_t)((Y0 + 1) * W) * 4 + k;
                    if (vx0) atomicAdd(row + (size_t)X0 * 4,       bb * wy[k]);
                    if (vx1) atomicAdd(row + (size_t)(X0 + 1) * 4, a  * wy[k]);
                }
            }
        }
    }
}

// ---------------------------------------------------------------------------
// Kernel 2: fused reduce + finalize.
// Exact tiling: each warp owns 4 consecutive 512B chunks; each thread does 4
// independent, coalesced float4 loads (MLP=4). fp32 partials (16 values/thread,
// O(1) magnitude -> ~1e-7 error), promoted to double at warp level. Re-zeroes
// the image for the next graph replay. Last block computes -var(ddof=1).
// ---------------------------------------------------------------------------
__global__ void __launch_bounds__(256) reduce_final_kernel(float* __restrict__ out) {
    const int lane = threadIdx.x & 31;
    const int gwarp = (blockIdx.x * 256 + threadIdx.x) >> 5;
    const int base = gwarp * 128 + lane;          // float4 index

    const float4 v0 = g_image4[base];
    const float4 v1 = g_image4[base + 32];
    const float4 v2 = g_image4[base + 64];
    const float4 v3 = g_image4[base + 96];

    const float4 z4 = make_float4(0.f, 0.f, 0.f, 0.f);
    g_image4[base]      = z4;                     // re-zero for next replay
    g_image4[base + 32] = z4;
    g_image4[base + 64] = z4;
    g_image4[base + 96] = z4;

    float fs  = ((v0.x + v0.y) + (v0.z + v0.w)) + ((v1.x + v1.y) + (v1.z + v1.w))
              + ((v2.x + v2.y) + (v2.z + v2.w)) + ((v3.x + v3.y) + (v3.z + v3.w));
    float fs2 = (fmaf(v0.x, v0.x, v0.y * v0.y) + fmaf(v0.z, v0.z, v0.w * v0.w))
              + (fmaf(v1.x, v1.x, v1.y * v1.y) + fmaf(v1.z, v1.z, v1.w * v1.w))
              + (fmaf(v2.x, v2.x, v2.y * v2.y) + fmaf(v2.z, v2.z, v2.w * v2.w))
              + (fmaf(v3.x, v3.x, v3.y * v3.y) + fmaf(v3.z, v3.z, v3.w * v3.w));

    double s  = (double)fs;
    double s2 = (double)fs2;

    #pragma unroll
    for (int o = 16; o > 0; o >>= 1) {
        s  += __shfl_down_sync(0xFFFFFFFFu, s,  o);
        s2 += __shfl_down_sync(0xFFFFFFFFu, s2, o);
    }
    __shared__ double sh[2][8];
    const int wid = threadIdx.x >> 5;
    if (lane == 0) { sh[0][wid] = s; sh[1][wid] = s2; }
    __syncthreads();

    __shared__ bool is_last;
    if (threadIdx.x == 0) {
        double bs = 0.0, bs2 = 0.0;
        #pragma unroll
        for (int w = 0; w < 8; ++w) { bs += sh[0][w]; bs2 += sh[1][w]; }
        atomicAdd(&g_acc[0], bs);
        atomicAdd(&g_acc[1], bs2);
        __threadfence();
        unsigned int t = atomicAdd(&g_count, 1u);
        is_last = (t == RGRID - 1);
    }
    __syncthreads();

    if (is_last && threadIdx.x == 0) {
        const double sum   = g_acc[0];
        const double sumsq = g_acc[1];
        const double Nd    = (double)NIMG;
        const double var   = (sumsq - sum * sum / Nd) / (Nd - 1.0);
        out[0] = (float)(-var);
        // reset for next replay
        g_acc[0] = 0.0;
        g_acc[1] = 0.0;
        g_count  = 0u;
    }
}

// ---------------------------------------------------------------------------
extern "C" void kernel_launch(void* const* d_in, const int* in_sizes, int n_in,
                              void* d_out, int out_size)
{
    const float* flow;
    const float* spike;
    if (in_sizes[0] == 2 * NPIX) {
        flow  = (const float*)d_in[0];
        spike = (const float*)d_in[1];
    } else {
        flow  = (const float*)d_in[1];
        spike = (const float*)d_in[0];
    }
    float* out = (float*)d_out;

    splat_kernel<<<NPIX / 256, 256>>>(flow, spike);
    reduce_final_kernel<<<RGRID, 256>>>(out);
}

// round 8
// speedup vs baseline: 1.5369x; 1.0238x over previous
#include <cuda_runtime.h>
#include <cstdint>

// Problem constants
#define B  4
#define C  64
#define H  256
#define W  256
#define HW (H*W)              // 65536
#define NPIX (B*HW)           // 262144 source pixels
#define NIMG (C*HW)           // 4194304 image elements

#define RGRID 1024            // reduce grid: 1024*256 threads * 4 float4 = NIMG exactly

// Scratch image as float4 per (group, y, x): img4[g*HW + y*W + x] holds
// channels {4g..4g+3} of pixel (y,x). Warp lanes are consecutive x, so a
// warp's 32 float4 REDs to one corner land in few contiguous cache lines.
// __device__ globals are zero-initialized at load; reduce_final re-zeroes
// everything it consumes, so every kernel_launch call sees clean state.
__device__ float4       g_image4[NIMG / 4];   // 16 MB
__device__ double       g_acc[2];             // [0]=sum, [1]=sumsq
__device__ unsigned int g_count;              // block completion counter

// 8B vector RED (channel pair within a float4 cell; offsets 0/8 are 8B-aligned)
__device__ __forceinline__ void red2(float* ptr, float a, float b) {
    asm volatile("red.global.add.v2.f32 [%0], {%1,%2};"
                 :: "l"(ptr), "f"(a), "f"(b) : "memory");
}

// ---------------------------------------------------------------------------
// Kernel 1: forward bilinear splat, 4 channels per float4 RED.
// One thread per source pixel (b,y,x); loops over 16 channel groups.
// Displacement u*s_c is monotone in c -> endpoint channels decide whether the
// whole 4-group shares one corner cell (~94%). On straddle, the cell changes
// at most once across the group, so at most one channel-PAIR straddles:
// uniform pairs get v2 REDs, the straddling pair falls back to scalars.
// ---------------------------------------------------------------------------
__global__ void __launch_bounds__(256) splat_kernel(
    const float* __restrict__ flow,
    const float* __restrict__ spike)
{
    const int idx = blockIdx.x * blockDim.x + threadIdx.x;   // grid exact

    const int b = idx >> 16;          // / HW
    const int p = idx & (HW - 1);     // % HW
    const int y = p >> 8;             // / W
    const int x = p & (W - 1);        // % W

    const float u = flow[(size_t)b * 2 * HW + p];
    const float v = flow[(size_t)b * 2 * HW + HW + p];
    const float* sp = spike + (size_t)b * C * HW + p;

    const float xf = (float)x;
    const float yf = (float)y;

    #pragma unroll
    for (int g = 0; g < C / 4; ++g) {
        float val[4], wx[4], wy[4];
        int   x0[4], y0[4];

        #pragma unroll
        for (int k = 0; k < 4; ++k) {
            const int c = g * 4 + k;
            val[k] = __ldg(sp + (size_t)c * HW);
            const float s  = ((float)c - 31.5f) * (1.0f / 64.0f);
            const float xn = fmaf(u, s, xf);
            const float yn = fmaf(v, s, yf);
            const float fx = floorf(xn);
            const float fy = floorf(yn);
            wx[k] = xn - fx;
            wy[k] = yn - fy;
            x0[k] = (int)fx;
            y0[k] = (int)fy;
        }

        float4* plane = g_image4 + (size_t)g * HW;

        if ((x0[0] == x0[3]) & (y0[0] == y0[3])) {
            // ---- fast path: whole group shares one corner cell ----
            const int X0 = x0[0], Y0 = y0[0];

            float4 w00, w10, w01, w11;
            {
                float a0 = val[0] * wx[0], b0 = val[0] - a0;   // a=val*wx, b=val*(1-wx)
                float a1 = val[1] * wx[1], b1 = val[1] - a1;
                float a2 = val[2] * wx[2], b2 = val[2] - a2;
                float a3 = val[3] * wx[3], b3 = val[3] - a3;
                float q0 = 1.0f - wy[0], q1 = 1.0f - wy[1];
                float q2 = 1.0f - wy[2], q3 = 1.0f - wy[3];
                w00 = make_float4(b0*q0,    b1*q1,    b2*q2,    b3*q3);
                w10 = make_float4(a0*q0,    a1*q1,    a2*q2,    a3*q3);
                w01 = make_float4(b0*wy[0], b1*wy[1], b2*wy[2], b3*wy[3]);
                w11 = make_float4(a0*wy[0], a1*wy[1], a2*wy[2], a3*wy[3]);
            }

            const bool vx0 = (X0 >= 0)  & (X0 < W);
            const bool vx1 = (X0 >= -1) & (X0 < W - 1);

            if (Y0 >= 0 && Y0 < H) {
                float4* row = plane + Y0 * W;
                if (vx0) atomicAdd(row + X0,     w00);
                if (vx1) atomicAdd(row + X0 + 1, w10);
            }
            if (Y0 >= -1 && Y0 < H - 1) {
                float4* row = plane + (Y0 + 1) * W;
                if (vx0) atomicAdd(row + X0,     w01);
                if (vx1) atomicAdd(row + X0 + 1, w11);
            }
        } else {
            // ---- straddle: handle channel pairs {0,1} and {2,3} ----
            float* pf = reinterpret_cast<float*>(plane);

            #pragma unroll
            for (int h = 0; h < 2; ++h) {
                const int k0 = 2 * h;
                const int k1 = k0 + 1;

                if ((x0[k0] == x0[k1]) & (y0[k0] == y0[k1])) {
                    // uniform pair: v2 REDs at the 4 corners
                    const int X0 = x0[k0], Y0 = y0[k0];
                    const float a0 = val[k0] * wx[k0], b0 = val[k0] - a0;
                    const float a1 = val[k1] * wx[k1], b1 = val[k1] - a1;
                    const float q0 = 1.0f - wy[k0], q1 = 1.0f - wy[k1];

                    const bool vx0 = (X0 >= 0)  & (X0 < W);
                    const bool vx1 = (X0 >= -1) & (X0 < W - 1);

                    if (Y0 >= 0 && Y0 < H) {
                        float* row = pf + (size_t)(Y0 * W) * 4 + k0;
                        if (vx0) red2(row + (size_t)X0 * 4,       b0 * q0, b1 * q1);
                        if (vx1) red2(row + (size_t)(X0 + 1) * 4, a0 * q0, a1 * q1);
                    }
                    if (Y0 >= -1 && Y0 < H - 1) {
                        float* row = pf + (size_t)((Y0 + 1) * W) * 4 + k0;
                        if (vx0) red2(row + (size_t)X0 * 4,       b0 * wy[k0], b1 * wy[k1]);
                        if (vx1) red2(row + (size_t)(X0 + 1) * 4, a0 * wy[k0], a1 * wy[k1]);
                    }
                } else {
                    // straddling pair: scalar REDs per channel
                    #pragma unroll
                    for (int k = k0; k <= k1; ++k) {
                        const int X0 = x0[k], Y0 = y0[k];
                        const float a  = val[k] * wx[k];
                        const float bb = val[k] - a;
                        const float q  = 1.0f - wy[k];

                        const bool vx0 = (X0 >= 0)  & (X0 < W);
                        const bool vx1 = (X0 >= -1) & (X0 < W - 1);

                        if (Y0 >= 0 && Y0 < H) {
                            float* row = pf + (size_t)(Y0 * W) * 4 + k;
                            if (vx0) atomicAdd(row + (size_t)X0 * 4,       bb * q);
                            if (vx1) atomicAdd(row + (size_t)(X0 + 1) * 4, a  * q);
                        }
                        if (Y0 >= -1 && Y0 < H - 1) {
                            float* row = pf + (size_t)((Y0 + 1) * W) * 4 + k;
                            if (vx0) atomicAdd(row + (size_t)X0 * 4,       bb * wy[k]);
                            if (vx1) atomicAdd(row + (size_t)(X0 + 1) * 4, a  * wy[k]);
                        }
                    }
                }
            }
        }
    }
}

// ---------------------------------------------------------------------------
// Kernel 2: fused reduce + finalize.
// Exact tiling: each warp owns 4 consecutive 512B chunks; each thread does 4
// independent, coalesced float4 loads (MLP=4). fp32 partials (16 values/thread,
// O(1) magnitude -> ~1e-7 error), promoted to double at warp level. Re-zeroes
// the image for the next graph replay. Last block computes -var(ddof=1).
// ---------------------------------------------------------------------------
__global__ void __launch_bounds__(256) reduce_final_kernel(float* __restrict__ out) {
    const int lane = threadIdx.x & 31;
    const int gwarp = (blockIdx.x * 256 + threadIdx.x) >> 5;
    const int base = gwarp * 128 + lane;          // float4 index

    const float4 v0 = g_image4[base];
    const float4 v1 = g_image4[base + 32];
    const float4 v2 = g_image4[base + 64];
    const float4 v3 = g_image4[base + 96];

    const float4 z4 = make_float4(0.f, 0.f, 0.f, 0.f);
    g_image4[base]      = z4;                     // re-zero for next replay
    g_image4[base + 32] = z4;
    g_image4[base + 64] = z4;
    g_image4[base + 96] = z4;

    float fs  = ((v0.x + v0.y) + (v0.z + v0.w)) + ((v1.x + v1.y) + (v1.z + v1.w))
              + ((v2.x + v2.y) + (v2.z + v2.w)) + ((v3.x + v3.y) + (v3.z + v3.w));
    float fs2 = (fmaf(v0.x, v0.x, v0.y * v0.y) + fmaf(v0.z, v0.z, v0.w * v0.w))
              + (fmaf(v1.x, v1.x, v1.y * v1.y) + fmaf(v1.z, v1.z, v1.w * v1.w))
              + (fmaf(v2.x, v2.x, v2.y * v2.y) + fmaf(v2.z, v2.z, v2.w * v2.w))
              + (fmaf(v3.x, v3.x, v3.y * v3.y) + fmaf(v3.z, v3.z, v3.w * v3.w));

    double s  = (double)fs;
    double s2 = (double)fs2;

    #pragma unroll
    for (int o = 16; o > 0; o >>= 1) {
        s  += __shfl_down_sync(0xFFFFFFFFu, s,  o);
        s2 += __shfl_down_sync(0xFFFFFFFFu, s2, o);
    }
    __shared__ double sh[2][8];
    const int wid = threadIdx.x >> 5;
    if (lane == 0) { sh[0][wid] = s; sh[1][wid] = s2; }
    __syncthreads();

    __shared__ bool is_last;
    if (threadIdx.x == 0) {
        double bs = 0.0, bs2 = 0.0;
        #pragma unroll
        for (int w = 0; w < 8; ++w) { bs += sh[0][w]; bs2 += sh[1][w]; }
        atomicAdd(&g_acc[0], bs);
        atomicAdd(&g_acc[1], bs2);
        __threadfence();
        unsigned int t = atomicAdd(&g_count, 1u);
        is_last = (t == RGRID - 1);
    }
    __syncthreads();

    if (is_last && threadIdx.x == 0) {
        const double sum   = g_acc[0];
        const double sumsq = g_acc[1];
        const double Nd    = (double)NIMG;
        const double var   = (sumsq - sum * sum / Nd) / (Nd - 1.0);
        out[0] = (float)(-var);
        // reset for next replay
        g_acc[0] = 0.0;
        g_acc[1] = 0.0;
        g_count  = 0u;
    }
}

// ---------------------------------------------------------------------------
extern "C" void kernel_launch(void* const* d_in, const int* in_sizes, int n_in,
                              void* d_out, int out_size)
{
    const float* flow;
    const float* spike;
    if (in_sizes[0] == 2 * NPIX) {
        flow  = (const float*)d_in[0];
        spike = (const float*)d_in[1];
    } else {
        flow  = (const float*)d_in[1];
        spike = (const float*)d_in[0];
    }
    float* out = (float*)d_out;

    splat_kernel<<<NPIX / 256, 256>>>(flow, spike);
    reduce_final_kernel<<<RGRID, 256>>>(out);
}